// round 2
// baseline (speedup 1.0000x reference)
#include <cuda_runtime.h>
#include <math.h>
#include <stdint.h>

#define BB   4
#define SS   1024
#define EE   4
#define HH   512
#define NHH  8
#define HDD  64
#define FFF  1024
#define LL   4
#define NTT  17
#define NR   63          // 2*MRP-1
#define NROWS (BB*SS)    // 4096

// ---------------- scratch (static device globals; no allocation) ----------------
__device__ float g_x[NROWS*EE];          // running residual (B,S,E)
__device__ float g_xn[NROWS*HH];         // LN(x@Wi+bi)
__device__ float g_qkv[NROWS*3*HH];      // qkv activations
__device__ float g_ao[NROWS*HH];         // attention output
__device__ float g_rsum[LL*NR];          // relemb[l].sum(-1)
__device__ int   g_mask[NROWS];          // normalized mask
__device__ int   g_flags[4];             // dtype detection flags

// ---------------- dtype detection ----------------
// mask may arrive as bool(u8), int32, float32 or bf16; patches as int32 or float32.
// Classify from bit patterns of the first 1024 32-bit words (deterministic).
__global__ void detect_kernel(const unsigned int* __restrict__ maskw,
                              const unsigned int* __restrict__ patw) {
    __shared__ int fl[4];
    int tid = threadIdx.x;
    if (tid < 4) fl[tid] = 0;
    __syncthreads();
    for (int i = tid; i < 1024; i += 256) {
        unsigned int w = maskw[i];
        if ((w & 0xFFFFu) == 0x3F80u) atomicOr(&fl[0], 1);   // bf16 "1.0" in low half
        if (w == 0x3F800000u)         atomicOr(&fl[1], 1);   // f32 1.0
        if (w > 1u)                   atomicOr(&fl[2], 1);   // not plain int 0/1 -> u8-packed
        unsigned int p = patw[i];
        if (p > 16u)                  atomicOr(&fl[3], 1);   // patches stored as float
    }
    __syncthreads();
    if (tid < 4) g_flags[tid] = fl[tid];
}

// ---------------- embedding + mask normalization ----------------
__global__ void embed_kernel(const void* __restrict__ maskp,
                             const void* __restrict__ patp,
                             const float* __restrict__ emb) {
    int i = blockIdx.x * blockDim.x + threadIdx.x;
    if (i >= NROWS) return;
    int fbf = g_flags[0], ff32 = g_flags[1], fu8 = g_flags[2], pf = g_flags[3];
    int m;
    if (fbf)       m = (((const unsigned short*)maskp)[i] != 0);
    else if (ff32) m = (((const float*)maskp)[i] != 0.0f);
    else if (fu8)  m = (((const unsigned char*)maskp)[i] != 0);
    else           m = (((const int*)maskp)[i] != 0);
    int p;
    if (pf) p = (int)(((const float*)patp)[i]);
    else    p = ((const int*)patp)[i];
    g_mask[i] = m;
    int src = m ? (NTT - 1) : p;
    #pragma unroll
    for (int e = 0; e < EE; e++)
        g_x[i*EE + e] = emb[src*EE + e];
}

// ---------------- relemb row sums ----------------
__global__ void rsum_kernel(const float* __restrict__ relemb) {
    int idx = threadIdx.x + blockIdx.x * blockDim.x;
    if (idx >= LL*NR) return;
    const float* p = relemb + (size_t)idx * HDD;
    float s = 0.f;
    #pragma unroll
    for (int d = 0; d < HDD; d++) s += p[d];
    g_rsum[idx] = s;
}

// ---------------- xp = x@Wi + bi ; xn = LN(xp)*g1+b1n  (fused) ----------------
__global__ void proj_ln_kernel(const float* __restrict__ Wi,
                               const float* __restrict__ bi,
                               const float* __restrict__ g1,
                               const float* __restrict__ b1n,
                               int l) {
    int row = blockIdx.x;
    int tid = threadIdx.x;               // 128 threads
    const float* W = Wi + (size_t)l*EE*HH;
    const float* bl = bi + (size_t)l*HH;
    const float* gl = g1 + (size_t)l*HH;
    const float* bn = b1n + (size_t)l*HH;
    float x0 = g_x[row*EE+0], x1 = g_x[row*EE+1], x2 = g_x[row*EE+2], x3 = g_x[row*EE+3];
    float xp[4];
    float s = 0.f, sq = 0.f;
    #pragma unroll
    for (int u = 0; u < 4; u++) {
        int j = tid + u*128;
        float v = bl[j] + x0*W[j] + x1*W[HH+j] + x2*W[2*HH+j] + x3*W[3*HH+j];
        xp[u] = v; s += v; sq += v*v;
    }
    #pragma unroll
    for (int off = 16; off > 0; off >>= 1) {
        s  += __shfl_down_sync(0xffffffffu, s,  off);
        sq += __shfl_down_sync(0xffffffffu, sq, off);
    }
    __shared__ float rs[4], rq[4];
    __shared__ float smean, sinv;
    if ((tid & 31) == 0) { rs[tid>>5] = s; rq[tid>>5] = sq; }
    __syncthreads();
    if (tid == 0) {
        float S = rs[0]+rs[1]+rs[2]+rs[3];
        float Q = rq[0]+rq[1]+rq[2]+rq[3];
        float m = S * (1.f/HH);
        float var = Q * (1.f/HH) - m*m;
        smean = m; sinv = rsqrtf(var + 1e-5f);
    }
    __syncthreads();
    float m = smean, inv = sinv;
    #pragma unroll
    for (int u = 0; u < 4; u++) {
        int j = tid + u*128;
        g_xn[(size_t)row*HH + j] = (xp[u]-m)*inv*gl[j] + bn[j];
    }
}

// ---------------- qkv = xn @ Wqkv + bqkv  (tiled SGEMM 64x64x16) ----------------
__global__ void gemm_qkv_kernel(const float* __restrict__ W,
                                const float* __restrict__ bias) {
    const int M = NROWS, N = 3*HH, K = HH;
    __shared__ float As[16][65];
    __shared__ float Bs[16][65];
    int tid = threadIdx.x;
    int tx = tid & 15, ty = tid >> 4;
    int row0 = blockIdx.y * 64, col0 = blockIdx.x * 64;
    float acc[4][4];
    #pragma unroll
    for (int i = 0; i < 4; i++)
        #pragma unroll
        for (int j = 0; j < 4; j++) acc[i][j] = 0.f;

    for (int k0 = 0; k0 < K; k0 += 16) {
        #pragma unroll
        for (int i = 0; i < 4; i++) {
            int e = tid + i*256;
            int am = e >> 4, ak = e & 15;
            As[ak][am] = g_xn[(size_t)(row0+am)*K + k0 + ak];
            int bk = e >> 6, bn = e & 63;
            Bs[bk][bn] = W[(size_t)(k0+bk)*N + col0 + bn];
        }
        __syncthreads();
        #pragma unroll
        for (int kk = 0; kk < 16; kk++) {
            float a[4], b[4];
            #pragma unroll
            for (int i = 0; i < 4; i++) a[i] = As[kk][ty*4+i];
            #pragma unroll
            for (int j = 0; j < 4; j++) b[j] = Bs[kk][tx*4+j];
            #pragma unroll
            for (int i = 0; i < 4; i++)
                #pragma unroll
                for (int j = 0; j < 4; j++) acc[i][j] += a[i]*b[j];
        }
        __syncthreads();
    }
    #pragma unroll
    for (int i = 0; i < 4; i++)
        #pragma unroll
        for (int j = 0; j < 4; j++)
            g_qkv[(size_t)(row0+ty*4+i)*N + col0+tx*4+j] = acc[i][j] + bias[col0+tx*4+j];
}

// ---------------- flash attention, 64x64 tiles, online softmax ----------------
#define ATT_SMEM_BYTES (18048*4)
__global__ void attn_kernel(int l) {
    extern __shared__ float sm[];
    float* qs   = sm;            // 64*65
    float* ks   = sm + 4160;     // 64*65
    float* vs   = sm + 8320;     // 64*65
    float* ps   = sm + 12480;    // 64*65
    float* sred = sm + 16640;    // 64*17
    float* mrun = sm + 17728;    // 64
    float* lsum = sm + 17792;    // 64
    float* cf   = sm + 17856;    // 64
    float* rb   = sm + 17920;    // 64 (63 used)
    float* mk   = sm + 17984;    // 64

    const int qt = blockIdx.x, h = blockIdx.y, b = blockIdx.z;
    const int tid = threadIdx.x;
    const int tx = tid & 15, ty = tid >> 4;
    const int qb = ty << 2, cb = tx << 2;

    if (tid < NR) rb[tid] = g_rsum[l*NR + tid];
    if (tid < 64) { mrun[tid] = -1e30f; lsum[tid] = 0.f; }

    {
        const float* qp = g_qkv + ((size_t)(b*SS + qt*64)*3 + 0)*HH + h*HDD;
        #pragma unroll
        for (int i = 0; i < 16; i++) {
            int e = tid + i*256;
            int r = e >> 6, c = e & 63;
            qs[r*65 + c] = qp[(size_t)r*(3*HH) + c];
        }
    }

    float o[4][4];
    #pragma unroll
    for (int i = 0; i < 4; i++)
        #pragma unroll
        for (int j = 0; j < 4; j++) o[i][j] = 0.f;

    for (int kt = 0; kt < 16; kt++) {
        __syncthreads();
        const float* kp = g_qkv + ((size_t)(b*SS + kt*64)*3 + 1)*HH + h*HDD;
        const float* vp = g_qkv + ((size_t)(b*SS + kt*64)*3 + 2)*HH + h*HDD;
        #pragma unroll
        for (int i = 0; i < 16; i++) {
            int e = tid + i*256;
            int r = e >> 6, c = e & 63;
            ks[r*65 + c] = kp[(size_t)r*(3*HH) + c];
            vs[r*65 + c] = vp[(size_t)r*(3*HH) + c];
        }
        if (tid < 64) mk[tid] = (float)g_mask[b*SS + kt*64 + tid];
        __syncthreads();

        // s = q @ k^T
        float sc[4][4];
        #pragma unroll
        for (int i = 0; i < 4; i++)
            #pragma unroll
            for (int j = 0; j < 4; j++) sc[i][j] = 0.f;
        #pragma unroll 8
        for (int kk = 0; kk < 64; kk++) {
            float a0 = qs[(qb+0)*65+kk], a1 = qs[(qb+1)*65+kk];
            float a2 = qs[(qb+2)*65+kk], a3 = qs[(qb+3)*65+kk];
            float b0 = ks[(cb+0)*65+kk], b1 = ks[(cb+1)*65+kk];
            float b2 = ks[(cb+2)*65+kk], b3 = ks[(cb+3)*65+kk];
            sc[0][0]+=a0*b0; sc[0][1]+=a0*b1; sc[0][2]+=a0*b2; sc[0][3]+=a0*b3;
            sc[1][0]+=a1*b0; sc[1][1]+=a1*b1; sc[1][2]+=a1*b2; sc[1][3]+=a1*b3;
            sc[2][0]+=a2*b0; sc[2][1]+=a2*b1; sc[2][2]+=a2*b2; sc[2][3]+=a2*b3;
            sc[3][0]+=a3*b0; sc[3][1]+=a3*b1; sc[3][2]+=a3*b2; sc[3][3]+=a3*b3;
        }
        // scale + relpos bias + mask, local row max
        #pragma unroll
        for (int i = 0; i < 4; i++) {
            float rm = -1e30f;
            int qrow = qt*64 + qb + i;
            #pragma unroll
            for (int j = 0; j < 4; j++) {
                int krow = kt*64 + cb + j;
                int d = qrow - krow + 31;
                d = d < 0 ? 0 : (d > 62 ? 62 : d);
                float v = sc[i][j]*0.125f + rb[d];
                if (mk[cb+j] != 0.f && qrow != krow) v = -1e30f;
                sc[i][j] = v;
                rm = fmaxf(rm, v);
            }
            sred[(qb+i)*17 + tx] = rm;
        }
        __syncthreads();
        if (tid < 64) {
            float tm = sred[tid*17];
            #pragma unroll
            for (int t = 1; t < 16; t++) tm = fmaxf(tm, sred[tid*17+t]);
            float mo = mrun[tid];
            float mn = fmaxf(mo, tm);
            cf[tid] = __expf(mo - mn);
            mrun[tid] = mn;
        }
        __syncthreads();
        // p = exp(s - m), rescale o, per-row partial sums
        #pragma unroll
        for (int i = 0; i < 4; i++) {
            float mi = mrun[qb+i];
            float ci = cf[qb+i];
            float rsum_i = 0.f;
            #pragma unroll
            for (int j = 0; j < 4; j++) {
                float p = (sc[i][j] > -1e29f) ? __expf(sc[i][j] - mi) : 0.f;
                ps[(qb+i)*65 + cb + j] = p;
                rsum_i += p;
                o[i][j] *= ci;
            }
            sred[(qb+i)*17 + tx] = rsum_i;
        }
        __syncthreads();
        if (tid < 64) {
            float sa = 0.f;
            #pragma unroll
            for (int t = 0; t < 16; t++) sa += sred[tid*17+t];
            lsum[tid] = lsum[tid]*cf[tid] + sa;
        }
        // o += p @ v
        #pragma unroll 8
        for (int kk = 0; kk < 64; kk++) {
            float p0 = ps[(qb+0)*65+kk], p1 = ps[(qb+1)*65+kk];
            float p2 = ps[(qb+2)*65+kk], p3 = ps[(qb+3)*65+kk];
            float v0 = vs[kk*65 + cb + 0], v1 = vs[kk*65 + cb + 1];
            float v2 = vs[kk*65 + cb + 2], v3 = vs[kk*65 + cb + 3];
            o[0][0]+=p0*v0; o[0][1]+=p0*v1; o[0][2]+=p0*v2; o[0][3]+=p0*v3;
            o[1][0]+=p1*v0; o[1][1]+=p1*v1; o[1][2]+=p1*v2; o[1][3]+=p1*v3;
            o[2][0]+=p2*v0; o[2][1]+=p2*v1; o[2][2]+=p2*v2; o[2][3]+=p2*v3;
            o[3][0]+=p3*v0; o[3][1]+=p3*v1; o[3][2]+=p3*v2; o[3][3]+=p3*v3;
        }
    }
    __syncthreads();
    float* aop = g_ao + (size_t)(b*SS + qt*64)*HH + h*HDD;
    #pragma unroll
    for (int i = 0; i < 4; i++) {
        float inv = 1.f / lsum[qb+i];
        #pragma unroll
        for (int j = 0; j < 4; j++)
            aop[(size_t)(qb+i)*HH + cb + j] = o[i][j]*inv;
    }
}

// ---------------- x += ao@Wo + bo; LN(E); FFN; x += ff  (all fused, per row) ----
__global__ void post_attn_kernel(const float* __restrict__ Wo,
                                 const float* __restrict__ bo,
                                 const float* __restrict__ g2,
                                 const float* __restrict__ b2n,
                                 const float* __restrict__ Wf1,
                                 const float* __restrict__ bf1,
                                 const float* __restrict__ Wf2,
                                 const float* __restrict__ bf2,
                                 int l) {
    int row = blockIdx.x;
    int tid = threadIdx.x;   // 128 threads
    __shared__ float4 red[128];
    __shared__ float tsh[4], xnsh[4];

    const float4* Wo4 = (const float4*)(Wo + (size_t)l*HH*EE);
    float4 acc = make_float4(0.f,0.f,0.f,0.f);
    for (int k = tid; k < HH; k += 128) {
        float a = g_ao[(size_t)row*HH + k];
        float4 w = Wo4[k];
        acc.x += a*w.x; acc.y += a*w.y; acc.z += a*w.z; acc.w += a*w.w;
    }
    red[tid] = acc;
    __syncthreads();
    for (int sft = 64; sft > 0; sft >>= 1) {
        if (tid < sft) {
            red[tid].x += red[tid+sft].x; red[tid].y += red[tid+sft].y;
            red[tid].z += red[tid+sft].z; red[tid].w += red[tid+sft].w;
        }
        __syncthreads();
    }
    if (tid == 0) {
        float t[4];
        const float* r0 = &red[0].x;
        #pragma unroll
        for (int e = 0; e < 4; e++) t[e] = g_x[row*EE+e] + r0[e] + bo[l*EE+e];
        float m = (t[0]+t[1]+t[2]+t[3]) * 0.25f;
        float var = 0.f;
        #pragma unroll
        for (int e = 0; e < 4; e++) { float d = t[e]-m; var += d*d; }
        var *= 0.25f;
        float inv = rsqrtf(var + 1e-5f);
        #pragma unroll
        for (int e = 0; e < 4; e++) {
            tsh[e] = t[e];
            xnsh[e] = (t[e]-m)*inv*g2[l*EE+e] + b2n[l*EE+e];
        }
    }
    __syncthreads();
    float xn0 = xnsh[0], xn1 = xnsh[1], xn2 = xnsh[2], xn3 = xnsh[3];
    const float* W1 = Wf1 + (size_t)l*EE*FFF;
    const float* b1 = bf1 + (size_t)l*FFF;
    const float4* W2 = (const float4*)(Wf2 + (size_t)l*FFF*EE);
    float4 f = make_float4(0.f,0.f,0.f,0.f);
    for (int j = tid; j < FFF; j += 128) {
        float hv = b1[j] + xn0*W1[j] + xn1*W1[FFF+j] + xn2*W1[2*FFF+j] + xn3*W1[3*FFF+j];
        hv = fmaxf(hv, 0.f);
        float4 w = W2[j];
        f.x += hv*w.x; f.y += hv*w.y; f.z += hv*w.z; f.w += hv*w.w;
    }
    red[tid] = f;
    __syncthreads();
    for (int sft = 64; sft > 0; sft >>= 1) {
        if (tid < sft) {
            red[tid].x += red[tid+sft].x; red[tid].y += red[tid+sft].y;
            red[tid].z += red[tid+sft].z; red[tid].w += red[tid+sft].w;
        }
        __syncthreads();
    }
    if (tid == 0) {
        const float* r0 = &red[0].x;
        #pragma unroll
        for (int e = 0; e < 4; e++)
            g_x[row*EE+e] = tsh[e] + r0[e] + bf2[l*EE+e];
    }
}

// ---------------- out = x @ Wout + bout ----------------
__global__ void out_kernel(const float* __restrict__ Wout,
                           const float* __restrict__ bout,
                           float* __restrict__ out, int total) {
    int i = blockIdx.x * blockDim.x + threadIdx.x;
    if (i >= total) return;
    int r = i / NTT, n = i % NTT;
    float acc = bout[n];
    #pragma unroll
    for (int e = 0; e < 4; e++) acc += g_x[r*EE+e]*Wout[e*NTT+n];
    out[i] = acc;
}

// ---------------- launch ----------------
extern "C" void kernel_launch(void* const* d_in, const int* in_sizes, int n_in,
                              void* d_out, int out_size) {
    const float* emb    = (const float*)d_in[2];
    const float* Wi     = (const float*)d_in[3];
    const float* bi     = (const float*)d_in[4];
    const float* Wqkv   = (const float*)d_in[5];
    const float* bqkv   = (const float*)d_in[6];
    const float* Wo     = (const float*)d_in[7];
    const float* bo     = (const float*)d_in[8];
    const float* g1     = (const float*)d_in[9];
    const float* b1n    = (const float*)d_in[10];
    const float* Wf1    = (const float*)d_in[11];
    const float* bf1    = (const float*)d_in[12];
    const float* Wf2    = (const float*)d_in[13];
    const float* bf2    = (const float*)d_in[14];
    const float* g2     = (const float*)d_in[15];
    const float* b2n    = (const float*)d_in[16];
    const float* relemb = (const float*)d_in[17];
    const float* Wout   = (const float*)d_in[18];
    const float* bout   = (const float*)d_in[19];

    cudaFuncSetAttribute(attn_kernel, cudaFuncAttributeMaxDynamicSharedMemorySize, ATT_SMEM_BYTES);

    detect_kernel<<<1, 256>>>((const unsigned int*)d_in[1], (const unsigned int*)d_in[0]);
    embed_kernel<<<NROWS/256, 256>>>(d_in[1], d_in[0], emb);
    rsum_kernel<<<1, 256>>>(relemb);

    for (int l = 0; l < LL; l++) {
        proj_ln_kernel<<<NROWS, 128>>>(Wi, bi, g1, b1n, l);
        gemm_qkv_kernel<<<dim3((3*HH)/64, NROWS/64), 256>>>(
            Wqkv + (size_t)l*HH*3*HH, bqkv + (size_t)l*3*HH);
        attn_kernel<<<dim3(SS/64, NHH, BB), 256, ATT_SMEM_BYTES>>>(l);
        post_attn_kernel<<<NROWS, 128>>>(Wo, bo, g2, b2n, Wf1, bf1, Wf2, bf2, l);
    }
    out_kernel<<<(NROWS*NTT + 255)/256, 256>>>(Wout, bout, (float*)d_out, NROWS*NTT);
}

// round 4
// speedup vs baseline: 2.9506x; 2.9506x over previous
#include <cuda_runtime.h>
#include <math.h>
#include <stdint.h>

#define BB   4
#define SS   1024
#define EE   4
#define HH   512
#define NHH  8
#define HDD  64
#define FFF  1024
#define LL   4
#define NTT  17
#define NR   63
#define NROWS (BB*SS)    // 4096

// ---------------- scratch ----------------
__device__ float g_x[NROWS*EE];
__device__ float g_xn[NROWS*HH];
__device__ float g_qkv[NROWS*3*HH];
__device__ float g_ao[NROWS*HH];
__device__ float g_rsum[LL*NR];
__device__ int   g_mask[NROWS];
__device__ int   g_flags[4];

// ---------------- tf32 helpers ----------------
__device__ __forceinline__ unsigned f2tf(float f) {
    unsigned u; asm("cvt.rna.tf32.f32 %0, %1;" : "=r"(u) : "f"(f)); return u;
}
__device__ __forceinline__ void mma8(float* c, unsigned a0, unsigned a1,
                                     unsigned a2, unsigned a3,
                                     unsigned b0, unsigned b1) {
    asm volatile(
        "mma.sync.aligned.m16n8k8.row.col.f32.tf32.tf32.f32 "
        "{%0,%1,%2,%3},{%4,%5,%6,%7},{%8,%9},{%0,%1,%2,%3};"
        : "+f"(c[0]), "+f"(c[1]), "+f"(c[2]), "+f"(c[3])
        : "r"(a0), "r"(a1), "r"(a2), "r"(a3), "r"(b0), "r"(b1));
}

// ---------------- dtype detection ----------------
__global__ void detect_kernel(const unsigned int* __restrict__ maskw,
                              const unsigned int* __restrict__ patw) {
    __shared__ int fl[4];
    int tid = threadIdx.x;
    if (tid < 4) fl[tid] = 0;
    __syncthreads();
    for (int i = tid; i < 1024; i += 256) {
        unsigned int w = maskw[i];
        if ((w & 0xFFFFu) == 0x3F80u) atomicOr(&fl[0], 1);
        if (w == 0x3F800000u)         atomicOr(&fl[1], 1);
        if (w > 1u)                   atomicOr(&fl[2], 1);
        unsigned int p = patw[i];
        if (p > 16u)                  atomicOr(&fl[3], 1);
    }
    __syncthreads();
    if (tid < 4) g_flags[tid] = fl[tid];
}

// ---------------- embedding + mask ----------------
__global__ void embed_kernel(const void* __restrict__ maskp,
                             const void* __restrict__ patp,
                             const float* __restrict__ emb) {
    int i = blockIdx.x * blockDim.x + threadIdx.x;
    if (i >= NROWS) return;
    int fbf = g_flags[0], ff32 = g_flags[1], fu8 = g_flags[2], pf = g_flags[3];
    int m;
    if (fbf)       m = (((const unsigned short*)maskp)[i] != 0);
    else if (ff32) m = (((const float*)maskp)[i] != 0.0f);
    else if (fu8)  m = (((const unsigned char*)maskp)[i] != 0);
    else           m = (((const int*)maskp)[i] != 0);
    int p;
    if (pf) p = (int)(((const float*)patp)[i]);
    else    p = ((const int*)patp)[i];
    g_mask[i] = m;
    int src = m ? (NTT - 1) : p;
    #pragma unroll
    for (int e = 0; e < EE; e++)
        g_x[i*EE + e] = emb[src*EE + e];
}

// ---------------- relemb row sums ----------------
__global__ void rsum_kernel(const float* __restrict__ relemb) {
    int idx = threadIdx.x + blockIdx.x * blockDim.x;
    if (idx >= LL*NR) return;
    const float* p = relemb + (size_t)idx * HDD;
    float s = 0.f;
    #pragma unroll
    for (int d = 0; d < HDD; d++) s += p[d];
    g_rsum[idx] = s;
}

// ---------------- xp = x@Wi + bi ; xn = LN(xp) ----------------
__global__ void proj_ln_kernel(const float* __restrict__ Wi,
                               const float* __restrict__ bi,
                               const float* __restrict__ g1,
                               const float* __restrict__ b1n,
                               int l) {
    int row = blockIdx.x;
    int tid = threadIdx.x;
    const float* W = Wi + (size_t)l*EE*HH;
    const float* bl = bi + (size_t)l*HH;
    const float* gl = g1 + (size_t)l*HH;
    const float* bn = b1n + (size_t)l*HH;
    float x0 = g_x[row*EE+0], x1 = g_x[row*EE+1], x2 = g_x[row*EE+2], x3 = g_x[row*EE+3];
    float xp[4];
    float s = 0.f, sq = 0.f;
    #pragma unroll
    for (int u = 0; u < 4; u++) {
        int j = tid + u*128;
        float v = bl[j] + x0*W[j] + x1*W[HH+j] + x2*W[2*HH+j] + x3*W[3*HH+j];
        xp[u] = v; s += v; sq += v*v;
    }
    #pragma unroll
    for (int off = 16; off > 0; off >>= 1) {
        s  += __shfl_down_sync(0xffffffffu, s,  off);
        sq += __shfl_down_sync(0xffffffffu, sq, off);
    }
    __shared__ float rs[4], rq[4];
    __shared__ float smean, sinv;
    if ((tid & 31) == 0) { rs[tid>>5] = s; rq[tid>>5] = sq; }
    __syncthreads();
    if (tid == 0) {
        float S = rs[0]+rs[1]+rs[2]+rs[3];
        float Q = rq[0]+rq[1]+rq[2]+rq[3];
        float m = S * (1.f/HH);
        float var = Q * (1.f/HH) - m*m;
        smean = m; sinv = rsqrtf(var + 1e-5f);
    }
    __syncthreads();
    float m = smean, inv = sinv;
    #pragma unroll
    for (int u = 0; u < 4; u++) {
        int j = tid + u*128;
        g_xn[(size_t)row*HH + j] = (xp[u]-m)*inv*gl[j] + bn[j];
    }
}

// ---------------- qkv = xn @ Wqkv + bqkv  (tf32 mma, 128x64 tile) ----------------
#define AST 36
#define BST 72
__global__ void __launch_bounds__(256)
gemm_qkv_kernel(const float* __restrict__ W, const float* __restrict__ bias) {
    const int N = 3*HH, K = HH;
    __shared__ float As[128*AST];
    __shared__ float Bs[32*BST];
    __shared__ float bsm[64];

    int tid = threadIdx.x;
    int w = tid >> 5, lane = tid & 31;
    int g = lane >> 2, t4 = lane & 3;
    int row0 = blockIdx.y * 128, col0 = blockIdx.x * 64;

    if (tid < 64) bsm[tid] = bias[col0 + tid];

    float c[8][4];
    #pragma unroll
    for (int nt = 0; nt < 8; nt++)
        #pragma unroll
        for (int j = 0; j < 4; j++) c[nt][j] = 0.f;

    for (int k0 = 0; k0 < K; k0 += 32) {
        __syncthreads();
        #pragma unroll
        for (int i = 0; i < 16; i++) {
            int e = tid + i*256;
            int r = e >> 5, cc = e & 31;
            As[r*AST + cc] = __uint_as_float(f2tf(g_xn[(size_t)(row0+r)*K + k0 + cc]));
        }
        #pragma unroll
        for (int i = 0; i < 8; i++) {
            int e = tid + i*256;
            int r = e >> 6, cc = e & 63;
            Bs[r*BST + cc] = __uint_as_float(f2tf(W[(size_t)(k0+r)*N + col0 + cc]));
        }
        __syncthreads();
        #pragma unroll
        for (int kk = 0; kk < 32; kk += 8) {
            int ab = (w*16 + g)*AST + kk + t4;
            unsigned a0 = __float_as_uint(As[ab]);
            unsigned a1 = __float_as_uint(As[ab + 8*AST]);
            unsigned a2 = __float_as_uint(As[ab + 4]);
            unsigned a3 = __float_as_uint(As[ab + 8*AST + 4]);
            #pragma unroll
            for (int nt = 0; nt < 8; nt++) {
                unsigned b0 = __float_as_uint(Bs[(kk+t4)*BST + nt*8 + g]);
                unsigned b1 = __float_as_uint(Bs[(kk+t4+4)*BST + nt*8 + g]);
                mma8(c[nt], a0, a1, a2, a3, b0, b1);
            }
        }
    }
    int grow0 = row0 + w*16 + g;
    #pragma unroll
    for (int nt = 0; nt < 8; nt++) {
        int lc = nt*8 + 2*t4;
        int gcol = col0 + lc;
        float2 v0 = make_float2(c[nt][0] + bsm[lc], c[nt][1] + bsm[lc+1]);
        float2 v1 = make_float2(c[nt][2] + bsm[lc], c[nt][3] + bsm[lc+1]);
        *(float2*)&g_qkv[(size_t)grow0*N + gcol]     = v0;
        *(float2*)&g_qkv[(size_t)(grow0+8)*N + gcol] = v1;
    }
}

// ---------------- flash attention, tf32 mma, 128 q-rows x 64-key tiles ----------
#define QST 68
#define ATT_FLOATS (128*QST + 64*QST + 64*QST + 128*QST + 64 + 64)
#define ATT_SMEM_BYTES (ATT_FLOATS*4)
__global__ void __launch_bounds__(256, 2) attn_kernel(int l) {
    extern __shared__ float sm[];
    float* qs = sm;                     // 128*68
    float* ks = sm + 128*QST;           // 64*68
    float* vs = sm + 192*QST;           // 64*68
    float* ps = sm + 256*QST;           // 128*68
    float* rb = sm + 384*QST;           // 64 (63 used)
    float* mk = sm + 384*QST + 64;      // 64

    const int qt = blockIdx.x, h = blockIdx.y, b = blockIdx.z;
    const int tid = threadIdx.x;
    const int w = tid >> 5, lane = tid & 31;
    const int g = lane >> 2, t4 = lane & 3;

    if (tid < NR) rb[tid] = g_rsum[l*NR + tid];

    {   // load Q (128 x 64), tf32-round into smem
        const float* qp = g_qkv + ((size_t)(b*SS + qt*128)*3 + 0)*HH + h*HDD;
        #pragma unroll
        for (int i = 0; i < 32; i++) {
            int e = tid + i*256;
            int r = e >> 6, cc = e & 63;
            qs[r*QST + cc] = __uint_as_float(f2tf(qp[(size_t)r*(3*HH) + cc]));
        }
    }

    const int lr0 = w*16 + g;              // local q rows owned by this thread
    const int qrow0 = qt*128 + lr0;
    const int qrow1 = qrow0 + 8;

    float o[8][4];
    #pragma unroll
    for (int nt = 0; nt < 8; nt++)
        #pragma unroll
        for (int j = 0; j < 4; j++) o[nt][j] = 0.f;
    float m0 = -1e30f, m1 = -1e30f, l0 = 0.f, l1 = 0.f;

    for (int kt = 0; kt < 16; kt++) {
        __syncthreads();
        const float* kp = g_qkv + ((size_t)(b*SS + kt*64)*3 + 1)*HH + h*HDD;
        const float* vp = g_qkv + ((size_t)(b*SS + kt*64)*3 + 2)*HH + h*HDD;
        #pragma unroll
        for (int i = 0; i < 16; i++) {
            int e = tid + i*256;
            int r = e >> 6, cc = e & 63;
            ks[r*QST + cc] = __uint_as_float(f2tf(kp[(size_t)r*(3*HH) + cc]));
            vs[r*QST + cc] = __uint_as_float(f2tf(vp[(size_t)r*(3*HH) + cc]));
        }
        if (tid < 64) mk[tid] = (float)g_mask[b*SS + kt*64 + tid];
        __syncthreads();

        // ---- S = Q K^T (16-row stripe per warp, 8 n-tiles of m16n8) ----
        float sc[8][4];
        #pragma unroll
        for (int nt = 0; nt < 8; nt++)
            #pragma unroll
            for (int j = 0; j < 4; j++) sc[nt][j] = 0.f;
        #pragma unroll
        for (int kk = 0; kk < 64; kk += 8) {
            int ab = lr0*QST + kk + t4;
            unsigned a0 = __float_as_uint(qs[ab]);
            unsigned a1 = __float_as_uint(qs[ab + 8*QST]);
            unsigned a2 = __float_as_uint(qs[ab + 4]);
            unsigned a3 = __float_as_uint(qs[ab + 8*QST + 4]);
            #pragma unroll
            for (int nt = 0; nt < 8; nt++) {
                unsigned b0 = __float_as_uint(ks[(nt*8+g)*QST + kk + t4]);
                unsigned b1 = __float_as_uint(ks[(nt*8+g)*QST + kk + t4 + 4]);
                mma8(sc[nt], a0, a1, a2, a3, b0, b1);
            }
        }

        // ---- scale + bias + mask; per-thread row maxima ----
        float mx0 = -1e30f, mx1 = -1e30f;
        #pragma unroll
        for (int nt = 0; nt < 8; nt++) {
            #pragma unroll
            for (int jj = 0; jj < 2; jj++) {
                int cc = nt*8 + 2*t4 + jj;
                int krow = kt*64 + cc;
                float mflag = mk[cc];
                int d0 = qrow0 - krow + 31; d0 = d0 < 0 ? 0 : (d0 > 62 ? 62 : d0);
                float v0 = sc[nt][jj]*0.125f + rb[d0];
                if (mflag != 0.f && qrow0 != krow) v0 = -1e30f;
                sc[nt][jj] = v0; mx0 = fmaxf(mx0, v0);
                int d1 = qrow1 - krow + 31; d1 = d1 < 0 ? 0 : (d1 > 62 ? 62 : d1);
                float v1 = sc[nt][jj+2]*0.125f + rb[d1];
                if (mflag != 0.f && qrow1 != krow) v1 = -1e30f;
                sc[nt][jj+2] = v1; mx1 = fmaxf(mx1, v1);
            }
        }
        // reduce max across the t4 quad (lanes g*4 + t4)
        #pragma unroll
        for (int off = 1; off < 4; off <<= 1) {
            mx0 = fmaxf(mx0, __shfl_xor_sync(0xffffffffu, mx0, off));
            mx1 = fmaxf(mx1, __shfl_xor_sync(0xffffffffu, mx1, off));
        }
        float mn0 = fmaxf(m0, mx0), mn1 = fmaxf(m1, mx1);
        float cf0 = __expf(m0 - mn0), cf1 = __expf(m1 - mn1);
        m0 = mn0; m1 = mn1;
        #pragma unroll
        for (int nt = 0; nt < 8; nt++) {
            o[nt][0] *= cf0; o[nt][1] *= cf0;
            o[nt][2] *= cf1; o[nt][3] *= cf1;
        }
        // ---- P = exp(S - m); store to warp-private ps rows; partial sums ----
        float s0 = 0.f, s1 = 0.f;
        #pragma unroll
        for (int nt = 0; nt < 8; nt++) {
            int cc = nt*8 + 2*t4;
            float p00 = (sc[nt][0] > -1e29f) ? __expf(sc[nt][0] - m0) : 0.f;
            float p01 = (sc[nt][1] > -1e29f) ? __expf(sc[nt][1] - m0) : 0.f;
            float p10 = (sc[nt][2] > -1e29f) ? __expf(sc[nt][2] - m1) : 0.f;
            float p11 = (sc[nt][3] > -1e29f) ? __expf(sc[nt][3] - m1) : 0.f;
            p00 = __uint_as_float(f2tf(p00)); p01 = __uint_as_float(f2tf(p01));
            p10 = __uint_as_float(f2tf(p10)); p11 = __uint_as_float(f2tf(p11));
            s0 += p00 + p01; s1 += p10 + p11;
            *(float2*)&ps[lr0*QST + cc]       = make_float2(p00, p01);
            *(float2*)&ps[(lr0+8)*QST + cc]   = make_float2(p10, p11);
        }
        #pragma unroll
        for (int off = 1; off < 4; off <<= 1) {
            s0 += __shfl_xor_sync(0xffffffffu, s0, off);
            s1 += __shfl_xor_sync(0xffffffffu, s1, off);
        }
        l0 = l0*cf0 + s0; l1 = l1*cf1 + s1;

        // ---- O += P V  (warp-local ps rows; no barrier needed) ----
        #pragma unroll
        for (int kk = 0; kk < 64; kk += 8) {
            int ab = lr0*QST + kk + t4;
            unsigned a0 = __float_as_uint(ps[ab]);
            unsigned a1 = __float_as_uint(ps[ab + 8*QST]);
            unsigned a2 = __float_as_uint(ps[ab + 4]);
            unsigned a3 = __float_as_uint(ps[ab + 8*QST + 4]);
            #pragma unroll
            for (int nt = 0; nt < 8; nt++) {
                unsigned b0 = __float_as_uint(vs[(kk+t4)*QST + nt*8 + g]);
                unsigned b1 = __float_as_uint(vs[(kk+t4+4)*QST + nt*8 + g]);
                mma8(o[nt], a0, a1, a2, a3, b0, b1);
            }
        }
    }

    // ---- normalize + write ----
    float inv0 = 1.f / l0, inv1 = 1.f / l1;
    float* aop = g_ao + (size_t)(b*SS + qt*128)*HH + h*HDD;
    #pragma unroll
    for (int nt = 0; nt < 8; nt++) {
        int cc = nt*8 + 2*t4;
        *(float2*)&aop[(size_t)lr0*HH + cc]     = make_float2(o[nt][0]*inv0, o[nt][1]*inv0);
        *(float2*)&aop[(size_t)(lr0+8)*HH + cc] = make_float2(o[nt][2]*inv1, o[nt][3]*inv1);
    }
}

// ---------------- x += ao@Wo + bo; LN(E); FFN; x += ff ----------------
__global__ void post_attn_kernel(const float* __restrict__ Wo,
                                 const float* __restrict__ bo,
                                 const float* __restrict__ g2,
                                 const float* __restrict__ b2n,
                                 const float* __restrict__ Wf1,
                                 const float* __restrict__ bf1,
                                 const float* __restrict__ Wf2,
                                 const float* __restrict__ bf2,
                                 int l) {
    int row = blockIdx.x;
    int tid = threadIdx.x;
    __shared__ float4 red[128];
    __shared__ float tsh[4], xnsh[4];

    const float4* Wo4 = (const float4*)(Wo + (size_t)l*HH*EE);
    float4 acc = make_float4(0.f,0.f,0.f,0.f);
    for (int k = tid; k < HH; k += 128) {
        float a = g_ao[(size_t)row*HH + k];
        float4 wv = Wo4[k];
        acc.x += a*wv.x; acc.y += a*wv.y; acc.z += a*wv.z; acc.w += a*wv.w;
    }
    red[tid] = acc;
    __syncthreads();
    for (int sft = 64; sft > 0; sft >>= 1) {
        if (tid < sft) {
            red[tid].x += red[tid+sft].x; red[tid].y += red[tid+sft].y;
            red[tid].z += red[tid+sft].z; red[tid].w += red[tid+sft].w;
        }
        __syncthreads();
    }
    if (tid == 0) {
        float t[4];
        const float* r0 = &red[0].x;
        #pragma unroll
        for (int e = 0; e < 4; e++) t[e] = g_x[row*EE+e] + r0[e] + bo[l*EE+e];
        float m = (t[0]+t[1]+t[2]+t[3]) * 0.25f;
        float var = 0.f;
        #pragma unroll
        for (int e = 0; e < 4; e++) { float d = t[e]-m; var += d*d; }
        var *= 0.25f;
        float inv = rsqrtf(var + 1e-5f);
        #pragma unroll
        for (int e = 0; e < 4; e++) {
            tsh[e] = t[e];
            xnsh[e] = (t[e]-m)*inv*g2[l*EE+e] + b2n[l*EE+e];
        }
    }
    __syncthreads();
    float xn0 = xnsh[0], xn1 = xnsh[1], xn2 = xnsh[2], xn3 = xnsh[3];
    const float* W1 = Wf1 + (size_t)l*EE*FFF;
    const float* b1 = bf1 + (size_t)l*FFF;
    const float4* W2 = (const float4*)(Wf2 + (size_t)l*FFF*EE);
    float4 f = make_float4(0.f,0.f,0.f,0.f);
    for (int j = tid; j < FFF; j += 128) {
        float hv = b1[j] + xn0*W1[j] + xn1*W1[FFF+j] + xn2*W1[2*FFF+j] + xn3*W1[3*FFF+j];
        hv = fmaxf(hv, 0.f);
        float4 wv = W2[j];
        f.x += hv*wv.x; f.y += hv*wv.y; f.z += hv*wv.z; f.w += hv*wv.w;
    }
    red[tid] = f;
    __syncthreads();
    for (int sft = 64; sft > 0; sft >>= 1) {
        if (tid < sft) {
            red[tid].x += red[tid+sft].x; red[tid].y += red[tid+sft].y;
            red[tid].z += red[tid+sft].z; red[tid].w += red[tid+sft].w;
        }
        __syncthreads();
    }
    if (tid == 0) {
        const float* r0 = &red[0].x;
        #pragma unroll
        for (int e = 0; e < 4; e++)
            g_x[row*EE+e] = tsh[e] + r0[e] + bf2[l*EE+e];
    }
}

// ---------------- out = x @ Wout + bout ----------------
__global__ void out_kernel(const float* __restrict__ Wout,
                           const float* __restrict__ bout,
                           float* __restrict__ out, int total) {
    int i = blockIdx.x * blockDim.x + threadIdx.x;
    if (i >= total) return;
    int r = i / NTT, n = i % NTT;
    float acc = bout[n];
    #pragma unroll
    for (int e = 0; e < 4; e++) acc += g_x[r*EE+e]*Wout[e*NTT+n];
    out[i] = acc;
}

// ---------------- launch ----------------
extern "C" void kernel_launch(void* const* d_in, const int* in_sizes, int n_in,
                              void* d_out, int out_size) {
    const float* emb    = (const float*)d_in[2];
    const float* Wi     = (const float*)d_in[3];
    const float* bi     = (const float*)d_in[4];
    const float* Wqkv   = (const float*)d_in[5];
    const float* bqkv   = (const float*)d_in[6];
    const float* Wo     = (const float*)d_in[7];
    const float* bo     = (const float*)d_in[8];
    const float* g1     = (const float*)d_in[9];
    const float* b1n    = (const float*)d_in[10];
    const float* Wf1    = (const float*)d_in[11];
    const float* bf1    = (const float*)d_in[12];
    const float* Wf2    = (const float*)d_in[13];
    const float* bf2    = (const float*)d_in[14];
    const float* g2     = (const float*)d_in[15];
    const float* b2n    = (const float*)d_in[16];
    const float* relemb = (const float*)d_in[17];
    const float* Wout   = (const float*)d_in[18];
    const float* bout   = (const float*)d_in[19];

    cudaFuncSetAttribute(attn_kernel, cudaFuncAttributeMaxDynamicSharedMemorySize, ATT_SMEM_BYTES);

    detect_kernel<<<1, 256>>>((const unsigned int*)d_in[1], (const unsigned int*)d_in[0]);
    embed_kernel<<<NROWS/256, 256>>>(d_in[1], d_in[0], emb);
    rsum_kernel<<<1, 256>>>(relemb);

    for (int l = 0; l < LL; l++) {
        proj_ln_kernel<<<NROWS, 128>>>(Wi, bi, g1, b1n, l);
        gemm_qkv_kernel<<<dim3((3*HH)/64, NROWS/128), 256>>>(
            Wqkv + (size_t)l*HH*3*HH, bqkv + (size_t)l*3*HH);
        attn_kernel<<<dim3(SS/128, NHH, BB), 256, ATT_SMEM_BYTES>>>(l);
        post_attn_kernel<<<NROWS, 128>>>(Wo, bo, g2, b2n, Wf1, bf1, Wf2, bf2, l);
    }
    out_kernel<<<(NROWS*NTT + 255)/256, 256>>>(Wout, bout, (float*)d_out, NROWS*NTT);
}

// round 6
// speedup vs baseline: 3.7449x; 1.2692x over previous
#include <cuda_runtime.h>
#include <math.h>
#include <stdint.h>

#define BB   4
#define SS   1024
#define EE   4
#define HH   512
#define NHH  8
#define HDD  64
#define FFF  1024
#define LL   4
#define NTT  17
#define NR   63
#define NROWS (BB*SS)    // 4096

// ---------------- scratch ----------------
__device__ float g_x[NROWS*EE];
__device__ float g_xn[NROWS*HH];          // tf32-rounded
__device__ float g_qkv[NROWS*3*HH];       // tf32-rounded
__device__ float g_ao[NROWS*HH];
__device__ float g_rsum[LL*NR];
__device__ int   g_mask[NROWS];
__device__ int   g_flags[4];
__device__ float g_wqkv[LL*HH*3*HH];      // tf32-rounded Wqkv

// ---------------- helpers ----------------
__device__ __forceinline__ unsigned f2tf(float f) {
    unsigned u; asm("cvt.rna.tf32.f32 %0, %1;" : "=r"(u) : "f"(f)); return u;
}
__device__ __forceinline__ void mma8(float* c, unsigned a0, unsigned a1,
                                     unsigned a2, unsigned a3,
                                     unsigned b0, unsigned b1) {
    asm volatile(
        "mma.sync.aligned.m16n8k8.row.col.f32.tf32.tf32.f32 "
        "{%0,%1,%2,%3},{%4,%5,%6,%7},{%8,%9},{%0,%1,%2,%3};"
        : "+f"(c[0]), "+f"(c[1]), "+f"(c[2]), "+f"(c[3])
        : "r"(a0), "r"(a1), "r"(a2), "r"(a3), "r"(b0), "r"(b1));
}
__device__ __forceinline__ unsigned smem_u32(const void* p) {
    return (unsigned)__cvta_generic_to_shared(p);
}
__device__ __forceinline__ void cp16(unsigned s, const void* g) {
    asm volatile("cp.async.ca.shared.global [%0],[%1],16;\n" :: "r"(s), "l"(g));
}
__device__ __forceinline__ void cp_commit() { asm volatile("cp.async.commit_group;\n"); }
template<int N> __device__ __forceinline__ void cp_wait() {
    asm volatile("cp.async.wait_group %0;\n" :: "n"(N));
}

// ---------------- dtype detection ----------------
__global__ void detect_kernel(const unsigned int* __restrict__ maskw,
                              const unsigned int* __restrict__ patw) {
    __shared__ int fl[4];
    int tid = threadIdx.x;
    if (tid < 4) fl[tid] = 0;
    __syncthreads();
    for (int i = tid; i < 1024; i += 256) {
        unsigned int w = maskw[i];
        if ((w & 0xFFFFu) == 0x3F80u) atomicOr(&fl[0], 1);
        if (w == 0x3F800000u)         atomicOr(&fl[1], 1);
        if (w > 1u)                   atomicOr(&fl[2], 1);
        unsigned int p = patw[i];
        if (p > 16u)                  atomicOr(&fl[3], 1);
    }
    __syncthreads();
    if (tid < 4) g_flags[tid] = fl[tid];
}

// ---------------- embedding + mask ----------------
__global__ void embed_kernel(const void* __restrict__ maskp,
                             const void* __restrict__ patp,
                             const float* __restrict__ emb) {
    int i = blockIdx.x * blockDim.x + threadIdx.x;
    if (i >= NROWS) return;
    int fbf = g_flags[0], ff32 = g_flags[1], fu8 = g_flags[2], pf = g_flags[3];
    int m;
    if (fbf)       m = (((const unsigned short*)maskp)[i] != 0);
    else if (ff32) m = (((const float*)maskp)[i] != 0.0f);
    else if (fu8)  m = (((const unsigned char*)maskp)[i] != 0);
    else           m = (((const int*)maskp)[i] != 0);
    int p;
    if (pf) p = (int)(((const float*)patp)[i]);
    else    p = ((const int*)patp)[i];
    g_mask[i] = m;
    int src = m ? (NTT - 1) : p;
    #pragma unroll
    for (int e = 0; e < EE; e++)
        g_x[i*EE + e] = emb[src*EE + e];
}

// ---------------- relemb row sums ----------------
__global__ void rsum_kernel(const float* __restrict__ relemb) {
    int idx = threadIdx.x + blockIdx.x * blockDim.x;
    if (idx >= LL*NR) return;
    const float* p = relemb + (size_t)idx * HDD;
    float s = 0.f;
    #pragma unroll
    for (int d = 0; d < HDD; d++) s += p[d];
    g_rsum[idx] = s;
}

// ---------------- Wqkv -> tf32-rounded copy ----------------
__global__ void round_w_kernel(const float* __restrict__ W) {
    int i = blockIdx.x * blockDim.x + threadIdx.x;   // float4 index
    float4 v = ((const float4*)W)[i];
    v.x = __uint_as_float(f2tf(v.x));
    v.y = __uint_as_float(f2tf(v.y));
    v.z = __uint_as_float(f2tf(v.z));
    v.w = __uint_as_float(f2tf(v.w));
    ((float4*)g_wqkv)[i] = v;
}

// ---------------- xp = x@Wi + bi ; xn = tf32(LN(xp)) ----------------
__global__ void proj_ln_kernel(const float* __restrict__ Wi,
                               const float* __restrict__ bi,
                               const float* __restrict__ g1,
                               const float* __restrict__ b1n,
                               int l) {
    int row = blockIdx.x;
    int tid = threadIdx.x;
    const float* W = Wi + (size_t)l*EE*HH;
    const float* bl = bi + (size_t)l*HH;
    const float* gl = g1 + (size_t)l*HH;
    const float* bn = b1n + (size_t)l*HH;
    float x0 = g_x[row*EE+0], x1 = g_x[row*EE+1], x2 = g_x[row*EE+2], x3 = g_x[row*EE+3];
    float xp[4];
    float s = 0.f, sq = 0.f;
    #pragma unroll
    for (int u = 0; u < 4; u++) {
        int j = tid + u*128;
        float v = bl[j] + x0*W[j] + x1*W[HH+j] + x2*W[2*HH+j] + x3*W[3*HH+j];
        xp[u] = v; s += v; sq += v*v;
    }
    #pragma unroll
    for (int off = 16; off > 0; off >>= 1) {
        s  += __shfl_down_sync(0xffffffffu, s,  off);
        sq += __shfl_down_sync(0xffffffffu, sq, off);
    }
    __shared__ float rs[4], rq[4];
    __shared__ float smean, sinv;
    if ((tid & 31) == 0) { rs[tid>>5] = s; rq[tid>>5] = sq; }
    __syncthreads();
    if (tid == 0) {
        float S = rs[0]+rs[1]+rs[2]+rs[3];
        float Q = rq[0]+rq[1]+rq[2]+rq[3];
        float m = S * (1.f/HH);
        float var = Q * (1.f/HH) - m*m;
        smean = m; sinv = rsqrtf(var + 1e-5f);
    }
    __syncthreads();
    float m = smean, inv = sinv;
    #pragma unroll
    for (int u = 0; u < 4; u++) {
        int j = tid + u*128;
        g_xn[(size_t)row*HH + j] =
            __uint_as_float(f2tf((xp[u]-m)*inv*gl[j] + bn[j]));
    }
}

// ---------------- qkv = xn @ Wqkv + bqkv (tf32 mma, cp.async double-buffered) ---
#define AST 36
#define BST 72
#define GEMM_SMEM_FLOATS (2*128*AST + 2*32*BST + 64)
#define GEMM_SMEM_BYTES  (GEMM_SMEM_FLOATS*4)
__global__ void __launch_bounds__(256)
gemm_qkv_kernel(int l, const float* __restrict__ bias_all) {
    extern __shared__ float sm[];
    float* As = sm;                       // 2 x 128*AST
    float* Bs = sm + 2*128*AST;           // 2 x 32*BST
    float* bsm = sm + 2*128*AST + 2*32*BST;

    const int N = 3*HH, K = HH;
    const float* W = g_wqkv + (size_t)l*HH*3*HH;      // device-side symbol offset
    const float* bias = bias_all + (size_t)l*3*HH;

    int tid = threadIdx.x;
    int w = tid >> 5, lane = tid & 31;
    int g = lane >> 2, t4 = lane & 3;
    int row0 = blockIdx.y * 128, col0 = blockIdx.x * 64;

    if (tid < 64) bsm[tid] = bias[col0 + tid];

    auto issue = [&](int stage) {
        int buf = stage & 1;
        int k0 = stage * 32;
        float* Ab = As + buf*128*AST;
        float* Bb = Bs + buf*32*BST;
        #pragma unroll
        for (int i = 0; i < 4; i++) {
            int id = tid + i*256;          // 1024 chunks: 128 rows x 8
            int r = id >> 3, c = id & 7;
            cp16(smem_u32(&Ab[r*AST + c*4]), &g_xn[(size_t)(row0+r)*K + k0 + c*4]);
        }
        #pragma unroll
        for (int i = 0; i < 2; i++) {
            int id = tid + i*256;          // 512 chunks: 32 rows x 16
            int r = id >> 4, c = id & 15;
            cp16(smem_u32(&Bb[r*BST + c*4]), &W[(size_t)(k0+r)*N + col0 + c*4]);
        }
    };

    float c[8][4];
    #pragma unroll
    for (int nt = 0; nt < 8; nt++)
        #pragma unroll
        for (int j = 0; j < 4; j++) c[nt][j] = 0.f;

    issue(0); cp_commit();
    for (int s = 0; s < 16; s++) {
        if (s < 15) { issue(s+1); cp_commit(); cp_wait<1>(); }
        else cp_wait<0>();
        __syncthreads();
        const float* A = As + (s&1)*128*AST;
        const float* B = Bs + (s&1)*32*BST;
        #pragma unroll
        for (int kk = 0; kk < 32; kk += 8) {
            int ab = (w*16 + g)*AST + kk + t4;
            unsigned a0 = __float_as_uint(A[ab]);
            unsigned a1 = __float_as_uint(A[ab + 8*AST]);
            unsigned a2 = __float_as_uint(A[ab + 4]);
            unsigned a3 = __float_as_uint(A[ab + 8*AST + 4]);
            #pragma unroll
            for (int nt = 0; nt < 8; nt++) {
                unsigned b0 = __float_as_uint(B[(kk+t4)*BST + nt*8 + g]);
                unsigned b1 = __float_as_uint(B[(kk+t4+4)*BST + nt*8 + g]);
                mma8(c[nt], a0, a1, a2, a3, b0, b1);
            }
        }
        __syncthreads();
    }
    int grow0 = row0 + w*16 + g;
    #pragma unroll
    for (int nt = 0; nt < 8; nt++) {
        int lc = nt*8 + 2*t4;
        int gcol = col0 + lc;
        float2 v0 = make_float2(__uint_as_float(f2tf(c[nt][0] + bsm[lc])),
                                __uint_as_float(f2tf(c[nt][1] + bsm[lc+1])));
        float2 v1 = make_float2(__uint_as_float(f2tf(c[nt][2] + bsm[lc])),
                                __uint_as_float(f2tf(c[nt][3] + bsm[lc+1])));
        *(float2*)&g_qkv[(size_t)grow0*N + gcol]     = v0;
        *(float2*)&g_qkv[(size_t)(grow0+8)*N + gcol] = v1;
    }
}

// ---------------- flash attention (tf32 mma, cp.async double-buffered K/V) ------
#define QST 68
#define VST 72
#define OFF_KS (128*QST)
#define OFF_VS (OFF_KS + 2*64*QST)
#define OFF_RB (OFF_VS + 2*64*VST)
#define OFF_MK (OFF_RB + 64)
#define ATT_SMEM_FLOATS (OFF_MK + 128)
#define ATT_SMEM_BYTES  (ATT_SMEM_FLOATS*4)
__global__ void __launch_bounds__(256, 2) attn_kernel(int l) {
    extern __shared__ float sm[];
    float* qs = sm;
    float* ks = sm + OFF_KS;
    float* vs = sm + OFF_VS;
    float* rb = sm + OFF_RB;
    int*   mki = (int*)(sm + OFF_MK);

    const int qt = blockIdx.x, h = blockIdx.y, b = blockIdx.z;
    const int tid = threadIdx.x;
    const int w = tid >> 5, lane = tid & 31;
    const int g = lane >> 2, t4 = lane & 3;

    if (tid < NR) rb[tid] = g_rsum[l*NR + tid];

    const float* qp = g_qkv + ((size_t)(b*SS + qt*128)*3 + 0)*HH + h*HDD;

    auto issue = [&](int stage) {
        int buf = stage & 1;
        const float* kp = g_qkv + ((size_t)(b*SS + stage*64)*3 + 1)*HH + h*HDD;
        const float* vp = g_qkv + ((size_t)(b*SS + stage*64)*3 + 2)*HH + h*HDD;
        float* kb = ks + buf*64*QST;
        float* vb = vs + buf*64*VST;
        #pragma unroll
        for (int i = 0; i < 4; i++) {
            int id = tid + i*256;         // 1024 chunks: 64 rows x 16
            int r = id >> 4, c = id & 15;
            cp16(smem_u32(&kb[r*QST + c*4]), &kp[(size_t)r*(3*HH) + c*4]);
            cp16(smem_u32(&vb[r*VST + c*4]), &vp[(size_t)r*(3*HH) + c*4]);
        }
        if (tid < 16)
            cp16(smem_u32(&mki[buf*64 + tid*4]), &g_mask[b*SS + stage*64 + tid*4]);
    };

    // prologue: Q + stage 0 in one group
    #pragma unroll
    for (int i = 0; i < 8; i++) {
        int id = tid + i*256;             // 2048 chunks: 128 rows x 16
        int r = id >> 4, c = id & 15;
        cp16(smem_u32(&qs[r*QST + c*4]), &qp[(size_t)r*(3*HH) + c*4]);
    }
    issue(0); cp_commit();

    const int lr0 = w*16 + g;
    const int qrow0 = qt*128 + lr0;
    const int qrow1 = qrow0 + 8;

    float o[8][4];
    #pragma unroll
    for (int nt = 0; nt < 8; nt++)
        #pragma unroll
        for (int j = 0; j < 4; j++) o[nt][j] = 0.f;
    float m0 = -1e30f, m1 = -1e30f, l0 = 0.f, l1 = 0.f;

    for (int kt = 0; kt < 16; kt++) {
        if (kt < 15) { issue(kt+1); cp_commit(); cp_wait<1>(); }
        else cp_wait<0>();
        __syncthreads();
        const int buf = kt & 1;
        const float* kb = ks + buf*64*QST;
        const float* vb = vs + buf*64*VST;
        const int*   mb = mki + buf*64;

        // ---- S = Q K^T ----
        float sc[8][4];
        #pragma unroll
        for (int nt = 0; nt < 8; nt++)
            #pragma unroll
            for (int j = 0; j < 4; j++) sc[nt][j] = 0.f;
        #pragma unroll
        for (int kk = 0; kk < 64; kk += 8) {
            int ab = lr0*QST + kk + t4;
            unsigned a0 = __float_as_uint(qs[ab]);
            unsigned a1 = __float_as_uint(qs[ab + 8*QST]);
            unsigned a2 = __float_as_uint(qs[ab + 4]);
            unsigned a3 = __float_as_uint(qs[ab + 8*QST + 4]);
            #pragma unroll
            for (int nt = 0; nt < 8; nt++) {
                unsigned b0 = __float_as_uint(kb[(nt*8+g)*QST + kk + t4]);
                unsigned b1 = __float_as_uint(kb[(nt*8+g)*QST + kk + t4 + 4]);
                mma8(sc[nt], a0, a1, a2, a3, b0, b1);
            }
        }

        // ---- scale + bias + mask; row maxima ----
        float mx0 = -1e30f, mx1 = -1e30f;
        #pragma unroll
        for (int nt = 0; nt < 8; nt++) {
            #pragma unroll
            for (int jj = 0; jj < 2; jj++) {
                int cc = nt*8 + 2*t4 + jj;
                int krow = kt*64 + cc;
                int mflag = mb[cc];
                int d0 = qrow0 - krow + 31; d0 = d0 < 0 ? 0 : (d0 > 62 ? 62 : d0);
                float v0 = sc[nt][jj]*0.125f + rb[d0];
                if (mflag && qrow0 != krow) v0 = -1e30f;
                sc[nt][jj] = v0; mx0 = fmaxf(mx0, v0);
                int d1 = qrow1 - krow + 31; d1 = d1 < 0 ? 0 : (d1 > 62 ? 62 : d1);
                float v1 = sc[nt][jj+2]*0.125f + rb[d1];
                if (mflag && qrow1 != krow) v1 = -1e30f;
                sc[nt][jj+2] = v1; mx1 = fmaxf(mx1, v1);
            }
        }
        #pragma unroll
        for (int off = 1; off < 4; off <<= 1) {
            mx0 = fmaxf(mx0, __shfl_xor_sync(0xffffffffu, mx0, off));
            mx1 = fmaxf(mx1, __shfl_xor_sync(0xffffffffu, mx1, off));
        }
        float mn0 = fmaxf(m0, mx0), mn1 = fmaxf(m1, mx1);
        float cf0 = __expf(m0 - mn0), cf1 = __expf(m1 - mn1);
        m0 = mn0; m1 = mn1;
        #pragma unroll
        for (int nt = 0; nt < 8; nt++) {
            o[nt][0] *= cf0; o[nt][1] *= cf0;
            o[nt][2] *= cf1; o[nt][3] *= cf1;
        }

        // ---- P = exp(S-m) in registers; C-frag -> A-frag via shfl; O += P V ----
        float s0 = 0.f, s1 = 0.f;
        int src0 = (lane & 28) | (t4 >> 1);
        int src1 = src0 + 2;
        bool hi = (t4 & 1);
        #pragma unroll
        for (int nt = 0; nt < 8; nt++) {
            float p00 = (sc[nt][0] > -1e29f) ? __expf(sc[nt][0] - m0) : 0.f;
            float p01 = (sc[nt][1] > -1e29f) ? __expf(sc[nt][1] - m0) : 0.f;
            float p10 = (sc[nt][2] > -1e29f) ? __expf(sc[nt][2] - m1) : 0.f;
            float p11 = (sc[nt][3] > -1e29f) ? __expf(sc[nt][3] - m1) : 0.f;
            p00 = __uint_as_float(f2tf(p00)); p01 = __uint_as_float(f2tf(p01));
            p10 = __uint_as_float(f2tf(p10)); p11 = __uint_as_float(f2tf(p11));
            s0 += p00 + p01; s1 += p10 + p11;
            float q00 = __shfl_sync(0xffffffffu, p00, src0);
            float q01 = __shfl_sync(0xffffffffu, p01, src0);
            float q10 = __shfl_sync(0xffffffffu, p10, src0);
            float q11 = __shfl_sync(0xffffffffu, p11, src0);
            float r00 = __shfl_sync(0xffffffffu, p00, src1);
            float r01 = __shfl_sync(0xffffffffu, p01, src1);
            float r10 = __shfl_sync(0xffffffffu, p10, src1);
            float r11 = __shfl_sync(0xffffffffu, p11, src1);
            unsigned a0 = __float_as_uint(hi ? q01 : q00);
            unsigned a1 = __float_as_uint(hi ? q11 : q10);
            unsigned a2 = __float_as_uint(hi ? r01 : r00);
            unsigned a3 = __float_as_uint(hi ? r11 : r10);
            int kk = nt*8;
            #pragma unroll
            for (int ont = 0; ont < 8; ont++) {
                unsigned b0 = __float_as_uint(vb[(kk+t4)*VST + ont*8 + g]);
                unsigned b1 = __float_as_uint(vb[(kk+t4+4)*VST + ont*8 + g]);
                mma8(o[ont], a0, a1, a2, a3, b0, b1);
            }
        }
        #pragma unroll
        for (int off = 1; off < 4; off <<= 1) {
            s0 += __shfl_xor_sync(0xffffffffu, s0, off);
            s1 += __shfl_xor_sync(0xffffffffu, s1, off);
        }
        l0 = l0*cf0 + s0; l1 = l1*cf1 + s1;
        __syncthreads();
    }

    float inv0 = 1.f / l0, inv1 = 1.f / l1;
    float* aop = g_ao + (size_t)(b*SS + qt*128)*HH + h*HDD;
    #pragma unroll
    for (int nt = 0; nt < 8; nt++) {
        int cc = nt*8 + 2*t4;
        *(float2*)&aop[(size_t)lr0*HH + cc]     = make_float2(o[nt][0]*inv0, o[nt][1]*inv0);
        *(float2*)&aop[(size_t)(lr0+8)*HH + cc] = make_float2(o[nt][2]*inv1, o[nt][3]*inv1);
    }
}

// ---------------- post-attn: warp-per-row, 4 rows per block, shfl-only ----------
__global__ void __launch_bounds__(128) post_attn_kernel(
        const float* __restrict__ Wo,  const float* __restrict__ bo,
        const float* __restrict__ g2,  const float* __restrict__ b2n,
        const float* __restrict__ Wf1, const float* __restrict__ bf1,
        const float* __restrict__ Wf2, const float* __restrict__ bf2, int l) {
    int w = threadIdx.x >> 5, lane = threadIdx.x & 31;
    int row = blockIdx.x * 4 + w;

    // part 1: ao @ Wo
    const float4* Wo4 = (const float4*)(Wo + (size_t)l*HH*EE);
    float4 acc = make_float4(0.f,0.f,0.f,0.f);
    for (int k = lane; k < HH; k += 32) {
        float a = g_ao[(size_t)row*HH + k];
        float4 wv = Wo4[k];
        acc.x += a*wv.x; acc.y += a*wv.y; acc.z += a*wv.z; acc.w += a*wv.w;
    }
    #pragma unroll
    for (int off = 16; off > 0; off >>= 1) {
        acc.x += __shfl_down_sync(0xffffffffu, acc.x, off);
        acc.y += __shfl_down_sync(0xffffffffu, acc.y, off);
        acc.z += __shfl_down_sync(0xffffffffu, acc.z, off);
        acc.w += __shfl_down_sync(0xffffffffu, acc.w, off);
    }
    float t0=0,t1=0,t2=0,t3=0, xn0=0,xn1=0,xn2=0,xn3=0;
    if (lane == 0) {
        t0 = g_x[row*EE+0] + acc.x + bo[l*EE+0];
        t1 = g_x[row*EE+1] + acc.y + bo[l*EE+1];
        t2 = g_x[row*EE+2] + acc.z + bo[l*EE+2];
        t3 = g_x[row*EE+3] + acc.w + bo[l*EE+3];
        float m = (t0+t1+t2+t3)*0.25f;
        float d0=t0-m, d1=t1-m, d2=t2-m, d3=t3-m;
        float var = (d0*d0+d1*d1+d2*d2+d3*d3)*0.25f;
        float inv = rsqrtf(var + 1e-5f);
        xn0 = d0*inv*g2[l*EE+0] + b2n[l*EE+0];
        xn1 = d1*inv*g2[l*EE+1] + b2n[l*EE+1];
        xn2 = d2*inv*g2[l*EE+2] + b2n[l*EE+2];
        xn3 = d3*inv*g2[l*EE+3] + b2n[l*EE+3];
    }
    xn0 = __shfl_sync(0xffffffffu, xn0, 0);
    xn1 = __shfl_sync(0xffffffffu, xn1, 0);
    xn2 = __shfl_sync(0xffffffffu, xn2, 0);
    xn3 = __shfl_sync(0xffffffffu, xn3, 0);

    // part 2: FFN
    const float* W1 = Wf1 + (size_t)l*EE*FFF;
    const float* b1 = bf1 + (size_t)l*FFF;
    const float4* W2 = (const float4*)(Wf2 + (size_t)l*FFF*EE);
    float4 f = make_float4(0.f,0.f,0.f,0.f);
    for (int j = lane; j < FFF; j += 32) {
        float hv = b1[j] + xn0*W1[j] + xn1*W1[FFF+j] + xn2*W1[2*FFF+j] + xn3*W1[3*FFF+j];
        hv = fmaxf(hv, 0.f);
        float4 wv = W2[j];
        f.x += hv*wv.x; f.y += hv*wv.y; f.z += hv*wv.z; f.w += hv*wv.w;
    }
    #pragma unroll
    for (int off = 16; off > 0; off >>= 1) {
        f.x += __shfl_down_sync(0xffffffffu, f.x, off);
        f.y += __shfl_down_sync(0xffffffffu, f.y, off);
        f.z += __shfl_down_sync(0xffffffffu, f.z, off);
        f.w += __shfl_down_sync(0xffffffffu, f.w, off);
    }
    if (lane == 0) {
        g_x[row*EE+0] = t0 + f.x + bf2[l*EE+0];
        g_x[row*EE+1] = t1 + f.y + bf2[l*EE+1];
        g_x[row*EE+2] = t2 + f.z + bf2[l*EE+2];
        g_x[row*EE+3] = t3 + f.w + bf2[l*EE+3];
    }
}

// ---------------- out = x @ Wout + bout ----------------
__global__ void out_kernel(const float* __restrict__ Wout,
                           const float* __restrict__ bout,
                           float* __restrict__ out, int total) {
    int i = blockIdx.x * blockDim.x + threadIdx.x;
    if (i >= total) return;
    int r = i / NTT, n = i % NTT;
    float acc = bout[n];
    #pragma unroll
    for (int e = 0; e < 4; e++) acc += g_x[r*EE+e]*Wout[e*NTT+n];
    out[i] = acc;
}

// ---------------- launch ----------------
extern "C" void kernel_launch(void* const* d_in, const int* in_sizes, int n_in,
                              void* d_out, int out_size) {
    const float* emb    = (const float*)d_in[2];
    const float* Wi     = (const float*)d_in[3];
    const float* bi     = (const float*)d_in[4];
    const float* Wqkv   = (const float*)d_in[5];
    const float* bqkv   = (const float*)d_in[6];
    const float* Wo     = (const float*)d_in[7];
    const float* bo     = (const float*)d_in[8];
    const float* g1     = (const float*)d_in[9];
    const float* b1n    = (const float*)d_in[10];
    const float* Wf1    = (const float*)d_in[11];
    const float* bf1    = (const float*)d_in[12];
    const float* Wf2    = (const float*)d_in[13];
    const float* bf2    = (const float*)d_in[14];
    const float* g2     = (const float*)d_in[15];
    const float* b2n    = (const float*)d_in[16];
    const float* relemb = (const float*)d_in[17];
    const float* Wout   = (const float*)d_in[18];
    const float* bout   = (const float*)d_in[19];

    cudaFuncSetAttribute(attn_kernel, cudaFuncAttributeMaxDynamicSharedMemorySize, ATT_SMEM_BYTES);
    cudaFuncSetAttribute(gemm_qkv_kernel, cudaFuncAttributeMaxDynamicSharedMemorySize, GEMM_SMEM_BYTES);

    detect_kernel<<<1, 256>>>((const unsigned int*)d_in[1], (const unsigned int*)d_in[0]);
    embed_kernel<<<NROWS/256, 256>>>(d_in[1], d_in[0], emb);
    rsum_kernel<<<1, 256>>>(relemb);
    round_w_kernel<<<(LL*HH*3*HH/4)/256, 256>>>(Wqkv);

    for (int l = 0; l < LL; l++) {
        proj_ln_kernel<<<NROWS, 128>>>(Wi, bi, g1, b1n, l);
        gemm_qkv_kernel<<<dim3((3*HH)/64, NROWS/128), 256, GEMM_SMEM_BYTES>>>(l, bqkv);
        attn_kernel<<<dim3(SS/128, NHH, BB), 256, ATT_SMEM_BYTES>>>(l);
        post_attn_kernel<<<NROWS/4, 128>>>(Wo, bo, g2, b2n, Wf1, bf1, Wf2, bf2, l);
    }
    out_kernel<<<(NROWS*NTT + 255)/256, 256>>>(Wout, bout, (float*)d_out, NROWS*NTT);
}

// round 10
// speedup vs baseline: 4.7689x; 1.2734x over previous
#include <cuda_runtime.h>
#include <cuda_bf16.h>
#include <math.h>
#include <stdint.h>

#define BB   4
#define SS   1024
#define EE   4
#define HH   512
#define NHH  8
#define HDD  64
#define FFF  1024
#define LL   4
#define NTT  17
#define NR   63
#define NROWS (BB*SS)    // 4096

// ---------------- scratch ----------------
__device__ float g_x[NROWS*EE];
__device__ float g_xn[NROWS*HH];              // tf32-rounded LN output
__device__ __nv_bfloat16 g_qkvh[NROWS*2*HH];  // [row][q(512,pre-scaled) | k(512)] bf16
__device__ __nv_bfloat16 g_vT[NROWS*HH];      // [(b*NH+h)*HD+d][s] bf16
__device__ float g_ao[NROWS*HH];
__device__ float g_rsum[LL*NR];
__device__ int   g_mask[NROWS];
__device__ int   g_flags[4];
__device__ float g_wqkv[LL*HH*3*HH];          // tf32-rounded Wqkv

// ---------------- helpers ----------------
__device__ __forceinline__ unsigned f2tf(float f) {
    unsigned u; asm("cvt.rna.tf32.f32 %0, %1;" : "=r"(u) : "f"(f)); return u;
}
__device__ __forceinline__ unsigned pack_bf16(float lo, float hi) {
    unsigned r; asm("cvt.rn.bf16x2.f32 %0, %1, %2;" : "=r"(r) : "f"(hi), "f"(lo));
    return r;
}
__device__ __forceinline__ void mma8(float* c, unsigned a0, unsigned a1,
                                     unsigned a2, unsigned a3,
                                     unsigned b0, unsigned b1) {
    asm volatile(
        "mma.sync.aligned.m16n8k8.row.col.f32.tf32.tf32.f32 "
        "{%0,%1,%2,%3},{%4,%5,%6,%7},{%8,%9},{%0,%1,%2,%3};"
        : "+f"(c[0]), "+f"(c[1]), "+f"(c[2]), "+f"(c[3])
        : "r"(a0), "r"(a1), "r"(a2), "r"(a3), "r"(b0), "r"(b1));
}
__device__ __forceinline__ void mma16(float* c, unsigned a0, unsigned a1,
                                      unsigned a2, unsigned a3,
                                      unsigned b0, unsigned b1) {
    asm volatile(
        "mma.sync.aligned.m16n8k16.row.col.f32.bf16.bf16.f32 "
        "{%0,%1,%2,%3},{%4,%5,%6,%7},{%8,%9},{%0,%1,%2,%3};"
        : "+f"(c[0]), "+f"(c[1]), "+f"(c[2]), "+f"(c[3])
        : "r"(a0), "r"(a1), "r"(a2), "r"(a3), "r"(b0), "r"(b1));
}
__device__ __forceinline__ unsigned smem_u32(const void* p) {
    return (unsigned)__cvta_generic_to_shared(p);
}
__device__ __forceinline__ void cp16(unsigned s, const void* g) {
    asm volatile("cp.async.ca.shared.global [%0],[%1],16;\n" :: "r"(s), "l"(g));
}
__device__ __forceinline__ void cp_commit() { asm volatile("cp.async.commit_group;\n"); }
template<int N> __device__ __forceinline__ void cp_wait() {
    asm volatile("cp.async.wait_group %0;\n" :: "n"(N));
}

// ---------------- dtype detection ----------------
__global__ void detect_kernel(const unsigned int* __restrict__ maskw,
                              const unsigned int* __restrict__ patw) {
    __shared__ int fl[4];
    int tid = threadIdx.x;
    if (tid < 4) fl[tid] = 0;
    __syncthreads();
    for (int i = tid; i < 1024; i += 256) {
        unsigned int w = maskw[i];
        if ((w & 0xFFFFu) == 0x3F80u) atomicOr(&fl[0], 1);
        if (w == 0x3F800000u)         atomicOr(&fl[1], 1);
        if (w > 1u)                   atomicOr(&fl[2], 1);
        unsigned int p = patw[i];
        if (p > 16u)                  atomicOr(&fl[3], 1);
    }
    __syncthreads();
    if (tid < 4) g_flags[tid] = fl[tid];
}

// ---------------- embedding + mask ----------------
__global__ void embed_kernel(const void* __restrict__ maskp,
                             const void* __restrict__ patp,
                             const float* __restrict__ emb) {
    int i = blockIdx.x * blockDim.x + threadIdx.x;
    if (i >= NROWS) return;
    int fbf = g_flags[0], ff32 = g_flags[1], fu8 = g_flags[2], pf = g_flags[3];
    int m;
    if (fbf)       m = (((const unsigned short*)maskp)[i] != 0);
    else if (ff32) m = (((const float*)maskp)[i] != 0.0f);
    else if (fu8)  m = (((const unsigned char*)maskp)[i] != 0);
    else           m = (((const int*)maskp)[i] != 0);
    int p;
    if (pf) p = (int)(((const float*)patp)[i]);
    else    p = ((const int*)patp)[i];
    g_mask[i] = m;
    int src = m ? (NTT - 1) : p;
    #pragma unroll
    for (int e = 0; e < EE; e++)
        g_x[i*EE + e] = emb[src*EE + e];
}

// ---------------- relemb row sums ----------------
__global__ void rsum_kernel(const float* __restrict__ relemb) {
    int idx = threadIdx.x + blockIdx.x * blockDim.x;
    if (idx >= LL*NR) return;
    const float* p = relemb + (size_t)idx * HDD;
    float s = 0.f;
    #pragma unroll
    for (int d = 0; d < HDD; d++) s += p[d];
    g_rsum[idx] = s;
}

// ---------------- Wqkv -> tf32-rounded copy ----------------
__global__ void round_w_kernel(const float* __restrict__ W) {
    int i = blockIdx.x * blockDim.x + threadIdx.x;
    float4 v = ((const float4*)W)[i];
    v.x = __uint_as_float(f2tf(v.x));
    v.y = __uint_as_float(f2tf(v.y));
    v.z = __uint_as_float(f2tf(v.z));
    v.w = __uint_as_float(f2tf(v.w));
    ((float4*)g_wqkv)[i] = v;
}

// ---------------- xp = x@Wi + bi ; xn = tf32(LN(xp)) ----------------
__global__ void proj_ln_kernel(const float* __restrict__ Wi,
                               const float* __restrict__ bi,
                               const float* __restrict__ g1,
                               const float* __restrict__ b1n,
                               int l) {
    int row = blockIdx.x;
    int tid = threadIdx.x;
    const float* W = Wi + (size_t)l*EE*HH;
    const float* bl = bi + (size_t)l*HH;
    const float* gl = g1 + (size_t)l*HH;
    const float* bn = b1n + (size_t)l*HH;
    float x0 = g_x[row*EE+0], x1 = g_x[row*EE+1], x2 = g_x[row*EE+2], x3 = g_x[row*EE+3];
    float xp[4];
    float s = 0.f, sq = 0.f;
    #pragma unroll
    for (int u = 0; u < 4; u++) {
        int j = tid + u*128;
        float v = bl[j] + x0*W[j] + x1*W[HH+j] + x2*W[2*HH+j] + x3*W[3*HH+j];
        xp[u] = v; s += v; sq += v*v;
    }
    #pragma unroll
    for (int off = 16; off > 0; off >>= 1) {
        s  += __shfl_down_sync(0xffffffffu, s,  off);
        sq += __shfl_down_sync(0xffffffffu, sq, off);
    }
    __shared__ float rs[4], rq[4];
    __shared__ float smean, sinv;
    if ((tid & 31) == 0) { rs[tid>>5] = s; rq[tid>>5] = sq; }
    __syncthreads();
    if (tid == 0) {
        float S = rs[0]+rs[1]+rs[2]+rs[3];
        float Q = rq[0]+rq[1]+rq[2]+rq[3];
        float m = S * (1.f/HH);
        float var = Q * (1.f/HH) - m*m;
        smean = m; sinv = rsqrtf(var + 1e-5f);
    }
    __syncthreads();
    float m = smean, inv = sinv;
    #pragma unroll
    for (int u = 0; u < 4; u++) {
        int j = tid + u*128;
        g_xn[(size_t)row*HH + j] =
            __uint_as_float(f2tf((xp[u]-m)*inv*gl[j] + bn[j]));
    }
}

// ---------------- qkv GEMM (tf32 mma, cp.async 2-buf); bf16 epilogue -----------
#define AST 36
#define BST 72
#define GEMM_SMEM_FLOATS (2*128*AST + 2*32*BST + 64)
#define GEMM_SMEM_BYTES  (GEMM_SMEM_FLOATS*4)
__global__ void __launch_bounds__(256)
gemm_qkv_kernel(int l, const float* __restrict__ bias_all) {
    extern __shared__ float sm[];
    float* As = sm;
    float* Bs = sm + 2*128*AST;
    float* bsm = sm + 2*128*AST + 2*32*BST;

    const int N = 3*HH, K = HH;
    const float* W = g_wqkv + (size_t)l*HH*3*HH;
    const float* bias = bias_all + (size_t)l*3*HH;

    int tid = threadIdx.x;
    int w = tid >> 5, lane = tid & 31;
    int g = lane >> 2, t4 = lane & 3;
    int row0 = blockIdx.y * 128, col0 = blockIdx.x * 64;

    if (tid < 64) bsm[tid] = bias[col0 + tid];

    auto issue = [&](int stage) {
        int buf = stage & 1;
        int k0 = stage * 32;
        float* Ab = As + buf*128*AST;
        float* Bb = Bs + buf*32*BST;
        #pragma unroll
        for (int i = 0; i < 4; i++) {
            int id = tid + i*256;
            int r = id >> 3, c = id & 7;
            cp16(smem_u32(&Ab[r*AST + c*4]), &g_xn[(size_t)(row0+r)*K + k0 + c*4]);
        }
        #pragma unroll
        for (int i = 0; i < 2; i++) {
            int id = tid + i*256;
            int r = id >> 4, c = id & 15;
            cp16(smem_u32(&Bb[r*BST + c*4]), &W[(size_t)(k0+r)*N + col0 + c*4]);
        }
    };

    float c[8][4];
    #pragma unroll
    for (int nt = 0; nt < 8; nt++)
        #pragma unroll
        for (int j = 0; j < 4; j++) c[nt][j] = 0.f;

    issue(0); cp_commit();
    for (int s = 0; s < 16; s++) {
        if (s < 15) { issue(s+1); cp_commit(); cp_wait<1>(); }
        else cp_wait<0>();
        __syncthreads();
        const float* A = As + (s&1)*128*AST;
        const float* B = Bs + (s&1)*32*BST;
        #pragma unroll
        for (int kk = 0; kk < 32; kk += 8) {
            int ab = (w*16 + g)*AST + kk + t4;
            unsigned a0 = __float_as_uint(A[ab]);
            unsigned a1 = __float_as_uint(A[ab + 8*AST]);
            unsigned a2 = __float_as_uint(A[ab + 4]);
            unsigned a3 = __float_as_uint(A[ab + 8*AST + 4]);
            #pragma unroll
            for (int nt = 0; nt < 8; nt++) {
                unsigned b0 = __float_as_uint(B[(kk+t4)*BST + nt*8 + g]);
                unsigned b1 = __float_as_uint(B[(kk+t4+4)*BST + nt*8 + g]);
                mma8(c[nt], a0, a1, a2, a3, b0, b1);
            }
        }
        __syncthreads();
    }
    int grow0 = row0 + w*16 + g;
    #pragma unroll
    for (int nt = 0; nt < 8; nt++) {
        int lc = nt*8 + 2*t4;
        int gcol = col0 + lc;
        float b0v = bsm[lc], b1v = bsm[lc+1];
        float c00 = c[nt][0] + b0v, c01 = c[nt][1] + b1v;
        float c10 = c[nt][2] + b0v, c11 = c[nt][3] + b1v;
        if (col0 < 2*HH) {
            // q (pre-scaled by 1/sqrt(HD)=0.125, exact) and k -> g_qkvh bf16
            float s = (col0 < HH) ? 0.125f : 1.0f;
            *(unsigned*)&g_qkvh[(size_t)grow0*(2*HH) + gcol]     = pack_bf16(s*c00, s*c01);
            *(unsigned*)&g_qkvh[(size_t)(grow0+8)*(2*HH) + gcol] = pack_bf16(s*c10, s*c11);
        } else {
            // v -> g_vT[(b*NH+h)*HD+d][s]  (transposed scatter)
            int hd = gcol - 2*HH;
            int h = hd >> 6, d = hd & 63;
            int bb = grow0 >> 10, s0 = grow0 & 1023;
            size_t base = ((size_t)((bb*NHH + h)*HDD + d))*SS;
            g_vT[base + s0]          = __float2bfloat16(c00);
            g_vT[base + SS + s0]     = __float2bfloat16(c01);
            g_vT[base + s0 + 8]      = __float2bfloat16(c10);
            g_vT[base + SS + s0 + 8] = __float2bfloat16(c11);
        }
    }
}

// ---------------- flash attention: bf16 m16n8k16, cp.async 2-buf K/V^T ---------
#define QSU 36                       // u32 stride for 64-bf16 rows
#define OFF_KSU (128*QSU)
#define OFF_VSU (OFF_KSU + 2*64*QSU)
#define OFF_RBU (OFF_VSU + 2*64*QSU)
#define OFF_MKU (OFF_RBU + 64)
#define ATT_SMEM_U32   (OFF_MKU + 128)
#define ATT_SMEM_BYTES (ATT_SMEM_U32*4)
__global__ void __launch_bounds__(256, 2) attn_kernel(int l) {
    extern __shared__ unsigned smu[];
    unsigned* qs = smu;
    unsigned* ks = smu + OFF_KSU;
    unsigned* vs = smu + OFF_VSU;
    float*    rb = (float*)(smu + OFF_RBU);
    int*     mki = (int*)(smu + OFF_MKU);

    const int qt = blockIdx.x, h = blockIdx.y, b = blockIdx.z;
    const int tid = threadIdx.x;
    const int w = tid >> 5, lane = tid & 31;
    const int g = lane >> 2, t4 = lane & 3;

    if (tid < NR) rb[tid] = g_rsum[l*NR + tid];

    const __nv_bfloat16* qp = g_qkvh + (size_t)(b*SS + qt*128)*(2*HH) + h*HDD;

    auto issue = [&](int stage) {
        int buf = stage & 1;
        const __nv_bfloat16* kp = g_qkvh + (size_t)(b*SS + stage*64)*(2*HH) + HH + h*HDD;
        const __nv_bfloat16* vp = g_vT + ((size_t)((b*NHH + h)*HDD))*SS + stage*64;
        unsigned* kb = ks + buf*64*QSU;
        unsigned* vb = vs + buf*64*QSU;
        #pragma unroll
        for (int i = 0; i < 2; i++) {
            int id = tid + i*256;           // 512 chunks: 64 rows x 8 (16B each)
            int r = id >> 3, c = id & 7;
            cp16(smem_u32(&kb[r*QSU + c*4]), kp + (size_t)r*(2*HH) + c*8);
            cp16(smem_u32(&vb[r*QSU + c*4]), vp + (size_t)r*SS + c*8);
        }
        if (tid < 16)
            cp16(smem_u32(&mki[buf*64 + tid*4]), &g_mask[b*SS + stage*64 + tid*4]);
    };

    // prologue: Q (128 rows x 8 chunks) + stage 0
    #pragma unroll
    for (int i = 0; i < 4; i++) {
        int id = tid + i*256;
        int r = id >> 3, c = id & 7;
        cp16(smem_u32(&qs[r*QSU + c*4]), qp + (size_t)r*(2*HH) + c*8);
    }
    issue(0); cp_commit();

    const int lr0 = w*16 + g;
    const int qrow0 = qt*128 + lr0;
    const int qrow1 = qrow0 + 8;

    float o[8][4];
    #pragma unroll
    for (int nt = 0; nt < 8; nt++)
        #pragma unroll
        for (int j = 0; j < 4; j++) o[nt][j] = 0.f;
    float m0 = -1e30f, m1 = -1e30f, l0 = 0.f, l1 = 0.f;

    for (int kt = 0; kt < 16; kt++) {
        if (kt < 15) { issue(kt+1); cp_commit(); cp_wait<1>(); }
        else cp_wait<0>();
        __syncthreads();
        const int buf = kt & 1;
        const unsigned* kb = ks + buf*64*QSU;
        const unsigned* vb = vs + buf*64*QSU;
        const int*      mb = mki + buf*64;

        // ---- S = Q K^T  (bf16 k16) ----
        float sc[8][4];
        #pragma unroll
        for (int nt = 0; nt < 8; nt++)
            #pragma unroll
            for (int j = 0; j < 4; j++) sc[nt][j] = 0.f;
        #pragma unroll
        for (int kc = 0; kc < 4; kc++) {
            int ab = lr0*QSU + kc*8 + t4;
            unsigned a0 = qs[ab];
            unsigned a1 = qs[ab + 8*QSU];
            unsigned a2 = qs[ab + 4];
            unsigned a3 = qs[ab + 8*QSU + 4];
            #pragma unroll
            for (int nt = 0; nt < 8; nt++) {
                int bbase = (nt*8 + g)*QSU + kc*8 + t4;
                mma16(sc[nt], a0, a1, a2, a3, kb[bbase], kb[bbase + 4]);
            }
        }

        // ---- bias + mask; row maxima (Q was pre-scaled by 1/8) ----
        float mx0 = -1e30f, mx1 = -1e30f;
        #pragma unroll
        for (int nt = 0; nt < 8; nt++) {
            #pragma unroll
            for (int jj = 0; jj < 2; jj++) {
                int cc = nt*8 + 2*t4 + jj;
                int krow = kt*64 + cc;
                int mflag = mb[cc];
                int d0 = qrow0 - krow + 31; d0 = d0 < 0 ? 0 : (d0 > 62 ? 62 : d0);
                float v0 = sc[nt][jj] + rb[d0];
                if (mflag && qrow0 != krow) v0 = -1e30f;
                sc[nt][jj] = v0; mx0 = fmaxf(mx0, v0);
                int d1 = qrow1 - krow + 31; d1 = d1 < 0 ? 0 : (d1 > 62 ? 62 : d1);
                float v1 = sc[nt][jj+2] + rb[d1];
                if (mflag && qrow1 != krow) v1 = -1e30f;
                sc[nt][jj+2] = v1; mx1 = fmaxf(mx1, v1);
            }
        }
        #pragma unroll
        for (int off = 1; off < 4; off <<= 1) {
            mx0 = fmaxf(mx0, __shfl_xor_sync(0xffffffffu, mx0, off));
            mx1 = fmaxf(mx1, __shfl_xor_sync(0xffffffffu, mx1, off));
        }
        float mn0 = fmaxf(m0, mx0), mn1 = fmaxf(m1, mx1);
        float cf0 = __expf(m0 - mn0), cf1 = __expf(m1 - mn1);
        m0 = mn0; m1 = mn1;
        #pragma unroll
        for (int nt = 0; nt < 8; nt++) {
            o[nt][0] *= cf0; o[nt][1] *= cf0;
            o[nt][2] *= cf1; o[nt][3] *= cf1;
        }

        // ---- P = exp(S-m); C-frag == A-frag for bf16 (no shuffles) ----
        float s0 = 0.f, s1 = 0.f;
        #pragma unroll
        for (int nt = 0; nt < 8; nt++) {
            float p00 = (sc[nt][0] > -1e29f) ? __expf(sc[nt][0] - m0) : 0.f;
            float p01 = (sc[nt][1] > -1e29f) ? __expf(sc[nt][1] - m0) : 0.f;
            float p10 = (sc[nt][2] > -1e29f) ? __expf(sc[nt][2] - m1) : 0.f;
            float p11 = (sc[nt][3] > -1e29f) ? __expf(sc[nt][3] - m1) : 0.f;
            s0 += p00 + p01; s1 += p10 + p11;
            sc[nt][0] = p00; sc[nt][1] = p01; sc[nt][2] = p10; sc[nt][3] = p11;
        }
        #pragma unroll
        for (int off = 1; off < 4; off <<= 1) {
            s0 += __shfl_xor_sync(0xffffffffu, s0, off);
            s1 += __shfl_xor_sync(0xffffffffu, s1, off);
        }
        l0 = l0*cf0 + s0; l1 = l1*cf1 + s1;

        // ---- O += P V  (A from packed C-fragments, B = V^T tile) ----
        #pragma unroll
        for (int j = 0; j < 4; j++) {
            unsigned a0 = pack_bf16(sc[2*j][0],   sc[2*j][1]);
            unsigned a1 = pack_bf16(sc[2*j][2],   sc[2*j][3]);
            unsigned a2 = pack_bf16(sc[2*j+1][0], sc[2*j+1][1]);
            unsigned a3 = pack_bf16(sc[2*j+1][2], sc[2*j+1][3]);
            #pragma unroll
            for (int ont = 0; ont < 8; ont++) {
                int bbase = (ont*8 + g)*QSU + j*8 + t4;
                mma16(o[ont], a0, a1, a2, a3, vb[bbase], vb[bbase + 4]);
            }
        }
        __syncthreads();
    }

    float inv0 = 1.f / l0, inv1 = 1.f / l1;
    float* aop = g_ao + (size_t)(b*SS + qt*128)*HH + h*HDD;
    #pragma unroll
    for (int nt = 0; nt < 8; nt++) {
        int cc = nt*8 + 2*t4;
        *(float2*)&aop[(size_t)lr0*HH + cc]     = make_float2(o[nt][0]*inv0, o[nt][1]*inv0);
        *(float2*)&aop[(size_t)(lr0+8)*HH + cc] = make_float2(o[nt][2]*inv1, o[nt][3]*inv1);
    }
}

// ---------------- post-attn: warp-per-row, 4 rows per block, shfl-only ----------
__global__ void __launch_bounds__(128) post_attn_kernel(
        const float* __restrict__ Wo,  const float* __restrict__ bo,
        const float* __restrict__ g2,  const float* __restrict__ b2n,
        const float* __restrict__ Wf1, const float* __restrict__ bf1,
        const float* __restrict__ Wf2, const float* __restrict__ bf2, int l) {
    int w = threadIdx.x >> 5, lane = threadIdx.x & 31;
    int row = blockIdx.x * 4 + w;

    const float4* Wo4 = (const float4*)(Wo + (size_t)l*HH*EE);
    float4 acc = make_float4(0.f,0.f,0.f,0.f);
    for (int k = lane; k < HH; k += 32) {
        float a = g_ao[(size_t)row*HH + k];
        float4 wv = Wo4[k];
        acc.x += a*wv.x; acc.y += a*wv.y; acc.z += a*wv.z; acc.w += a*wv.w;
    }
    #pragma unroll
    for (int off = 16; off > 0; off >>= 1) {
        acc.x += __shfl_down_sync(0xffffffffu, acc.x, off);
        acc.y += __shfl_down_sync(0xffffffffu, acc.y, off);
        acc.z += __shfl_down_sync(0xffffffffu, acc.z, off);
        acc.w += __shfl_down_sync(0xffffffffu, acc.w, off);
    }
    float t0=0,t1=0,t2=0,t3=0, xn0=0,xn1=0,xn2=0,xn3=0;
    if (lane == 0) {
        t0 = g_x[row*EE+0] + acc.x + bo[l*EE+0];
        t1 = g_x[row*EE+1] + acc.y + bo[l*EE+1];
        t2 = g_x[row*EE+2] + acc.z + bo[l*EE+2];
        t3 = g_x[row*EE+3] + acc.w + bo[l*EE+3];
        float m = (t0+t1+t2+t3)*0.25f;
        float d0=t0-m, d1=t1-m, d2=t2-m, d3=t3-m;
        float var = (d0*d0+d1*d1+d2*d2+d3*d3)*0.25f;
        float inv = rsqrtf(var + 1e-5f);
        xn0 = d0*inv*g2[l*EE+0] + b2n[l*EE+0];
        xn1 = d1*inv*g2[l*EE+1] + b2n[l*EE+1];
        xn2 = d2*inv*g2[l*EE+2] + b2n[l*EE+2];
        xn3 = d3*inv*g2[l*EE+3] + b2n[l*EE+3];
    }
    xn0 = __shfl_sync(0xffffffffu, xn0, 0);
    xn1 = __shfl_sync(0xffffffffu, xn1, 0);
    xn2 = __shfl_sync(0xffffffffu, xn2, 0);
    xn3 = __shfl_sync(0xffffffffu, xn3, 0);

    const float* W1 = Wf1 + (size_t)l*EE*FFF;
    const float* b1 = bf1 + (size_t)l*FFF;
    const float4* W2 = (const float4*)(Wf2 + (size_t)l*FFF*EE);
    float4 f = make_float4(0.f,0.f,0.f,0.f);
    for (int j = lane; j < FFF; j += 32) {
        float hv = b1[j] + xn0*W1[j] + xn1*W1[FFF+j] + xn2*W1[2*FFF+j] + xn3*W1[3*FFF+j];
        hv = fmaxf(hv, 0.f);
        float4 wv = W2[j];
        f.x += hv*wv.x; f.y += hv*wv.y; f.z += hv*wv.z; f.w += hv*wv.w;
    }
    #pragma unroll
    for (int off = 16; off > 0; off >>= 1) {
        f.x += __shfl_down_sync(0xffffffffu, f.x, off);
        f.y += __shfl_down_sync(0xffffffffu, f.y, off);
        f.z += __shfl_down_sync(0xffffffffu, f.z, off);
        f.w += __shfl_down_sync(0xffffffffu, f.w, off);
    }
    if (lane == 0) {
        g_x[row*EE+0] = t0 + f.x + bf2[l*EE+0];
        g_x[row*EE+1] = t1 + f.y + bf2[l*EE+1];
        g_x[row*EE+2] = t2 + f.z + bf2[l*EE+2];
        g_x[row*EE+3] = t3 + f.w + bf2[l*EE+3];
    }
}

// ---------------- out = x @ Wout + bout ----------------
__global__ void out_kernel(const float* __restrict__ Wout,
                           const float* __restrict__ bout,
                           float* __restrict__ out, int total) {
    int i = blockIdx.x * blockDim.x + threadIdx.x;
    if (i >= total) return;
    int r = i / NTT, n = i % NTT;
    float acc = bout[n];
    #pragma unroll
    for (int e = 0; e < 4; e++) acc += g_x[r*EE+e]*Wout[e*NTT+n];
    out[i] = acc;
}

// ---------------- launch ----------------
extern "C" void kernel_launch(void* const* d_in, const int* in_sizes, int n_in,
                              void* d_out, int out_size) {
    const float* emb    = (const float*)d_in[2];
    const float* Wi     = (const float*)d_in[3];
    const float* bi     = (const float*)d_in[4];
    const float* Wqkv   = (const float*)d_in[5];
    const float* bqkv   = (const float*)d_in[6];
    const float* Wo     = (const float*)d_in[7];
    const float* bo     = (const float*)d_in[8];
    const float* g1     = (const float*)d_in[9];
    const float* b1n    = (const float*)d_in[10];
    const float* Wf1    = (const float*)d_in[11];
    const float* bf1    = (const float*)d_in[12];
    const float* Wf2    = (const float*)d_in[13];
    const float* bf2    = (const float*)d_in[14];
    const float* g2     = (const float*)d_in[15];
    const float* b2n    = (const float*)d_in[16];
    const float* relemb = (const float*)d_in[17];
    const float* Wout   = (const float*)d_in[18];
    const float* bout   = (const float*)d_in[19];

    cudaFuncSetAttribute(attn_kernel, cudaFuncAttributeMaxDynamicSharedMemorySize, ATT_SMEM_BYTES);
    cudaFuncSetAttribute(gemm_qkv_kernel, cudaFuncAttributeMaxDynamicSharedMemorySize, GEMM_SMEM_BYTES);

    detect_kernel<<<1, 256>>>((const unsigned int*)d_in[1], (const unsigned int*)d_in[0]);
    embed_kernel<<<NROWS/256, 256>>>(d_in[1], d_in[0], emb);
    rsum_kernel<<<1, 256>>>(relemb);
    round_w_kernel<<<(LL*HH*3*HH/4)/256, 256>>>(Wqkv);

    for (int l = 0; l < LL; l++) {
        proj_ln_kernel<<<NROWS, 128>>>(Wi, bi, g1, b1n, l);
        gemm_qkv_kernel<<<dim3((3*HH)/64, NROWS/128), 256, GEMM_SMEM_BYTES>>>(l, bqkv);
        attn_kernel<<<dim3(SS/128, NHH, BB), 256, ATT_SMEM_BYTES>>>(l);
        post_attn_kernel<<<NROWS/4, 128>>>(Wo, bo, g2, b2n, Wf1, bf1, Wf2, bf2, l);
    }
    out_kernel<<<(NROWS*NTT + 255)/256, 256>>>(Wout, bout, (float*)d_out, NROWS*NTT);
}